// round 10
// baseline (speedup 1.0000x reference)
#include <cuda_runtime.h>
#include <cuda_bf16.h>

// GMMLoss: nll[b,m] = -logsumexp_n( c[b,n] - 0.5*dxy/sxy - 0.5*dz/sz ), out = mean(nll)
// SINGLE-KERNEL design:
//   - log2-domain, fixed LSE shift EST=40 (c2 < 36, distance terms <= 0)
//   - expanded-quadratic 5-FMA packed-f32x2 inner loop (round-5 proven geometry:
//     TN=128, TM=512, grid 32x8x4=1024 blocks of 128 threads)
//   - per-n params computed in a 1-n-per-thread prologue (no separate kernel)
//   - two-level last-block reduction: per-(b,mt) column chunk-sum + LSE by the
//     32nd-arriving chunk block (fixed-order sums => deterministic), then the
//     32nd-arriving column block does the fixed-order final mean.

#define BDIM 4
#define NDIM 4096
#define MDIM 4096
#define TN   128            // n per block chunk (== blockDim)
#define NCHUNK (NDIM / TN)  // 32
#define TM   512            // m per block (128 thr * 4)
#define NMT  (MDIM / TM)    // 8
#define BM   (BDIM * MDIM)  // 16384
#define NCOL (BDIM * NMT)   // 32 columns

#define EPSF     1e-8f
#define LOG2E    1.4426950408889634f
#define LN2      0.6931471805599453f
#define LOG_2PI  1.8378762f      /* log(2*3.14159) per reference */
#define ESTC     40.0f           /* fixed log2-domain LSE shift */
#define NHALFL2E (-0.7213475f)   /* -0.5*log2e */

// Static scratch (no allocation allowed)
__device__ float g_partial[NCHUNK * BM];   // [chunk][b*M+m]  (2 MB)
__device__ float g_colsum[NCOL];
__device__ unsigned int g_colcnt[NCOL];    // zero-init; self-reset each launch
__device__ unsigned int g_fin;             // zero-init; self-reset each launch

// ---------- packed f32x2 helpers ----------
__device__ __forceinline__ unsigned long long pk2(float lo, float hi) {
    unsigned long long r;
    asm("mov.b64 %0, {%1, %2};" : "=l"(r) : "f"(lo), "f"(hi));
    return r;
}
__device__ __forceinline__ void unpk2(unsigned long long v, float& lo, float& hi) {
    asm("mov.b64 {%0, %1}, %2;" : "=f"(lo), "=f"(hi) : "l"(v));
}
__device__ __forceinline__ unsigned long long fma2(unsigned long long a, unsigned long long b,
                                                   unsigned long long c) {
    unsigned long long r;
    asm("fma.rn.f32x2 %0, %1, %2, %3;" : "=l"(r) : "l"(a), "l"(b), "l"(c));
    return r;
}
__device__ __forceinline__ float ex2f(float x) {
    float r;
    asm("ex2.approx.ftz.f32 %0, %1;" : "=f"(r) : "f"(x));
    return r;
}

__global__ void __launch_bounds__(128) kmain(const float* __restrict__ xyz,
                                             const float* __restrict__ sigma,
                                             const float* __restrict__ tgt,
                                             float* __restrict__ out) {
    __shared__ float4 sm[TN * 3];  // 6 KB: per-n {K,K,a2,a2}{b2,b2,u,u}{v,v,w,w}
    int chunk = blockIdx.x;        // 0..31
    int mt    = blockIdx.y;        // 0..7
    int b     = blockIdx.z;        // 0..3
    int tid   = threadIdx.x;

    // --- prologue: 1 n per thread, params straight into shared ---
    {
        int idx = b * NDIM + chunk * TN + tid;
        float2 sg = ((const float2*)sigma)[idx];
        float sxy = sg.x + EPSF;
        float sz  = sg.y + EPSF;
        float c2 = -__log2f(sxy) - 0.5f * __log2f(sz) - 1.5f * LOG_2PI * LOG2E - ESTC;
        float a2 = __fdividef(NHALFL2E, sxy);
        float b2 = __fdividef(NHALFL2E, sz);
        float px = xyz[3 * idx + 0], py = xyz[3 * idx + 1], pz = xyz[3 * idx + 2];
        float K = fmaf(a2, fmaf(px, px, py * py), fmaf(b2, pz * pz, c2));
        float u = -2.0f * a2 * px;
        float v = -2.0f * a2 * py;
        float w = -2.0f * b2 * pz;
        sm[tid * 3 + 0] = make_float4(K, K, a2, a2);
        sm[tid * 3 + 1] = make_float4(b2, b2, u, u);
        sm[tid * 3 + 2] = make_float4(v, v, w, w);
    }

    // --- 4 targets per thread, packed into 2 m-pairs ---
    int m0 = mt * TM + tid;
    const float* t = tgt + (size_t)(b * MDIM + m0) * 3;
    float tx[4], ty[4], tz[4], sxyv[4], szv[4];
#pragma unroll
    for (int k = 0; k < 4; k++) {
        tx[k] = t[k * 128 * 3 + 0];
        ty[k] = t[k * 128 * 3 + 1];
        tz[k] = t[k * 128 * 3 + 2];
        sxyv[k] = fmaf(tx[k], tx[k], ty[k] * ty[k]);
        szv[k]  = tz[k] * tz[k];
    }
    unsigned long long TX0 = pk2(tx[0], tx[1]), TY0 = pk2(ty[0], ty[1]), TZ0 = pk2(tz[0], tz[1]);
    unsigned long long SXY0 = pk2(sxyv[0], sxyv[1]), SZ0 = pk2(szv[0], szv[1]);
    unsigned long long TX1 = pk2(tx[2], tx[3]), TY1 = pk2(ty[2], ty[3]), TZ1 = pk2(tz[2], tz[3]);
    unsigned long long SXY1 = pk2(sxyv[2], sxyv[3]), SZ1 = pk2(szv[2], szv[3]);

    float s0 = 0.f, s1 = 0.f, s2 = 0.f, s3 = 0.f;
    __syncthreads();

#pragma unroll 4
    for (int ni = 0; ni < TN; ni++) {
        const ulonglong2* q = (const ulonglong2*)(sm + ni * 3);
        ulonglong2 q0 = q[0];  // {K,K},{a2,a2}
        ulonglong2 q1 = q[1];  // {b2,b2},{u,u}
        ulonglong2 q2 = q[2];  // {v,v},{w,w}

        // pair 0 (m0, m0+128)
        {
            unsigned long long lp = fma2(q0.y, SXY0, q0.x);
            lp = fma2(q1.x, SZ0, lp);
            lp = fma2(q1.y, TX0, lp);
            lp = fma2(q2.x, TY0, lp);
            lp = fma2(q2.y, TZ0, lp);
            float lo, hi; unpk2(lp, lo, hi);
            s0 += ex2f(lo);
            s1 += ex2f(hi);
        }
        // pair 1 (m0+256, m0+384)
        {
            unsigned long long lp = fma2(q0.y, SXY1, q0.x);
            lp = fma2(q1.x, SZ1, lp);
            lp = fma2(q1.y, TX1, lp);
            lp = fma2(q2.x, TY1, lp);
            lp = fma2(q2.y, TZ1, lp);
            float lo, hi; unpk2(lp, lo, hi);
            s2 += ex2f(lo);
            s3 += ex2f(hi);
        }
    }

    int gmb = b * MDIM + mt * TM;  // column base in [0, BM)
    float* dst = g_partial + (size_t)chunk * BM + gmb + tid;
    dst[0]   = s0;
    dst[128] = s1;
    dst[256] = s2;
    dst[384] = s3;

    // --- level-1: last chunk block of this (b,mt) column reduces the column ---
    __threadfence();   // make this thread's partial stores globally visible
    __syncthreads();   // all threads' fences done before the flag bump
    int col = b * NMT + mt;  // 0..31
    __shared__ bool islast;
    if (tid == 0) {
        unsigned int old = atomicAdd(&g_colcnt[col], 1u);
        islast = (old == NCHUNK - 1);
    }
    __syncthreads();
    if (!islast) return;

    __threadfence();  // acquire: see all column partials
    float acc4 = 0.f;
#pragma unroll
    for (int k = 0; k < 4; k++) {
        int gm = gmb + tid + k * 128;
        float S = 0.f;
#pragma unroll
        for (int c = 0; c < NCHUNK; c++) S += g_partial[c * BM + gm];
        acc4 += -LN2 * (ESTC + __log2f(fmaxf(S, 1e-37f)));
    }
    __shared__ float red[128];
    red[tid] = acc4;
    __syncthreads();
    for (int s = 64; s > 0; s >>= 1) {
        if (tid < s) red[tid] += red[tid + s];
        __syncthreads();
    }

    // --- level-2: last column block does fixed-order final mean ---
    __shared__ bool isfinal;
    if (tid == 0) {
        g_colsum[col] = red[0];
        __threadfence();
        unsigned int old = atomicAdd(&g_fin, 1u);
        isfinal = (old == NCOL - 1);
    }
    __syncthreads();
    if (isfinal && tid == 0) {
        __threadfence();
        volatile float* cs = g_colsum;
        float acc = 0.f;
#pragma unroll
        for (int i = 0; i < NCOL; i++) acc += cs[i];
        out[0] = acc * (1.0f / (float)BM);
        // reset counters for next graph replay
#pragma unroll
        for (int i = 0; i < NCOL; i++) g_colcnt[i] = 0;
        g_fin = 0;
    }
}

extern "C" void kernel_launch(void* const* d_in, const int* in_sizes, int n_in,
                              void* d_out, int out_size) {
    const float* pred_xyz   = (const float*)d_in[0];  // (B,N,3)
    const float* pred_sigma = (const float*)d_in[1];  // (B,N,2)
    const float* target     = (const float*)d_in[2];  // (B,M,3)
    float* out = (float*)d_out;

    kmain<<<dim3(NCHUNK, NMT, BDIM), TN>>>(pred_xyz, pred_sigma, target, out);
}

// round 12
// speedup vs baseline: 1.3563x; 1.3563x over previous
#include <cuda_runtime.h>
#include <cuda_bf16.h>

// GMMLoss: nll[b,m] = -logsumexp_n( c[b,n] - 0.5*dxy/sxy - 0.5*dz/sz ), out = mean(nll)
// Proven 3-kernel split (round-5 structure). log2-domain, fixed LSE shift EST=40,
// expanded-quadratic 5-FMA packed-f32x2 inner loop.
// This round: TM 512->256 (1 m-pair/thread) => grid 2048, ~2x resident warps/SM,
// to saturate the MUFU (ex2) pipe which is the roofline (~16us floor).

#define BDIM 4
#define NDIM 4096
#define MDIM 4096
#define TN   128            // n per block chunk
#define NCHUNK (NDIM / TN)  // 32
#define TM   256            // m per block (128 thr * 2)
#define NMT  (MDIM / TM)    // 16
#define BM   (BDIM * MDIM)  // 16384

#define EPSF     1e-8f
#define LOG2E    1.4426950408889634f
#define LN2      0.6931471805599453f
#define LOG_2PI  1.8378762f      /* log(2*3.14159) per reference */
#define ESTC     40.0f           /* fixed log2-domain LSE shift */
#define NHALFL2E (-0.7213475f)   /* -0.5*log2e */

// Static scratch (no allocation allowed)
__device__ float g_params[BDIM * NDIM * 12];  // per n: {K,K,a2,a2, b2,b2,u,u, v,v,w,w}
__device__ float g_partial[NCHUNK * BM];      // [chunk][b*M+m]  (2 MB)
__device__ float g_bsum[64];
__device__ unsigned int g_flag;               // zero-init; self-resets each launch

// ---------- packed f32x2 helpers ----------
__device__ __forceinline__ unsigned long long pk2(float lo, float hi) {
    unsigned long long r;
    asm("mov.b64 %0, {%1, %2};" : "=l"(r) : "f"(lo), "f"(hi));
    return r;
}
__device__ __forceinline__ void unpk2(unsigned long long v, float& lo, float& hi) {
    asm("mov.b64 {%0, %1}, %2;" : "=f"(lo), "=f"(hi) : "l"(v));
}
__device__ __forceinline__ unsigned long long fma2(unsigned long long a, unsigned long long b,
                                                   unsigned long long c) {
    unsigned long long r;
    asm("fma.rn.f32x2 %0, %1, %2, %3;" : "=l"(r) : "l"(a), "l"(b), "l"(c));
    return r;
}
__device__ __forceinline__ float ex2f(float x) {
    float r;
    asm("ex2.approx.ftz.f32 %0, %1;" : "=f"(r) : "f"(x));
    return r;
}

// ---------- kernel 1: param precompute (pure map) ----------
__global__ void __launch_bounds__(128) kprep(const float* __restrict__ xyz,
                                             const float* __restrict__ sigma) {
    int idx = blockIdx.x * 128 + threadIdx.x;  // 0..16383 = b*N+n
    float2 sg = ((const float2*)sigma)[idx];
    float sxy = sg.x + EPSF;
    float sz  = sg.y + EPSF;
    float c2 = -__log2f(sxy) - 0.5f * __log2f(sz) - 1.5f * LOG_2PI * LOG2E - ESTC;
    float a2 = __fdividef(NHALFL2E, sxy);
    float b2 = __fdividef(NHALFL2E, sz);
    float px = xyz[3 * idx + 0], py = xyz[3 * idx + 1], pz = xyz[3 * idx + 2];
    float K = fmaf(a2, fmaf(px, px, py * py), fmaf(b2, pz * pz, c2));
    float u = -2.0f * a2 * px;
    float v = -2.0f * a2 * py;
    float w = -2.0f * b2 * pz;
    float4* o = (float4*)(g_params + (size_t)idx * 12);
    o[0] = make_float4(K, K, a2, a2);
    o[1] = make_float4(b2, b2, u, u);
    o[2] = make_float4(v, v, w, w);
}

// ---------- kernel 2: main pairwise sum-of-exp2 (1 m-pair per thread) ----------
__global__ void __launch_bounds__(128) kmain(const float* __restrict__ tgt) {
    __shared__ float4 sm[TN * 3];  // 6 KB: duplicated per-n params
    int chunk = blockIdx.x;        // 0..31
    int mt    = blockIdx.y;        // 0..15
    int b     = blockIdx.z;        // 0..3
    int tid   = threadIdx.x;

    // stage chunk params (simple LDG.128 -> STS.128 copy, as in the proven round-5 build)
    const float4* src = (const float4*)(g_params + (size_t)(b * NDIM + chunk * TN) * 12);
    for (int i = tid; i < TN * 3; i += 128) sm[i] = src[i];

    // 2 targets per thread -> one packed m-pair (m0, m0+128)
    int m0 = mt * TM + tid;
    const float* t = tgt + (size_t)(b * MDIM + m0) * 3;
    float tx0 = t[0],       ty0 = t[1],       tz0 = t[2];
    float tx1 = t[128 * 3], ty1 = t[128 * 3 + 1], tz1 = t[128 * 3 + 2];
    unsigned long long TX = pk2(tx0, tx1), TY = pk2(ty0, ty1), TZ = pk2(tz0, tz1);
    unsigned long long SXY = pk2(fmaf(tx0, tx0, ty0 * ty0), fmaf(tx1, tx1, ty1 * ty1));
    unsigned long long SZ  = pk2(tz0 * tz0, tz1 * tz1);

    float s0 = 0.f, s1 = 0.f;
    __syncthreads();

#pragma unroll 4
    for (int ni = 0; ni < TN; ni++) {
        const ulonglong2* q = (const ulonglong2*)(sm + ni * 3);
        ulonglong2 q0 = q[0];  // {K,K},{a2,a2}
        ulonglong2 q1 = q[1];  // {b2,b2},{u,u}
        ulonglong2 q2 = q[2];  // {v,v},{w,w}

        unsigned long long lp = fma2(q0.y, SXY, q0.x);
        lp = fma2(q1.x, SZ, lp);
        lp = fma2(q1.y, TX, lp);
        lp = fma2(q2.x, TY, lp);
        lp = fma2(q2.y, TZ, lp);
        float lo, hi; unpk2(lp, lo, hi);
        s0 += ex2f(lo);
        s1 += ex2f(hi);
    }

    float* dst = g_partial + (size_t)chunk * BM + b * MDIM + m0;
    dst[0]   = s0;
    dst[128] = s1;
}

// ---------- kernel 3: chunk-sum + LSE + full reduction (last-block pattern) ----------
__global__ void __launch_bounds__(256) kreduce(float* __restrict__ out) {
    int gm = blockIdx.x * 256 + threadIdx.x;  // 0..16383
    float S = 0.f;
#pragma unroll
    for (int c = 0; c < NCHUNK; c++) S += g_partial[(size_t)c * BM + gm];
    float nll = -LN2 * (ESTC + __log2f(fmaxf(S, 1e-37f)));

    __shared__ float red[256];
    red[threadIdx.x] = nll;
    __syncthreads();
    for (int s = 128; s > 0; s >>= 1) {
        if (threadIdx.x < s) red[threadIdx.x] += red[threadIdx.x + s];
        __syncthreads();
    }

    __shared__ bool islast;
    if (threadIdx.x == 0) {
        g_bsum[blockIdx.x] = red[0];
        __threadfence();
        unsigned int old = atomicAdd(&g_flag, 1u);
        islast = (old == 63u);
    }
    __syncthreads();

    if (islast && threadIdx.x == 0) {
        __threadfence();
        volatile float* bs = g_bsum;
        float acc = 0.f;
#pragma unroll
        for (int i = 0; i < 64; i++) acc += bs[i];
        out[0] = acc * (1.0f / (float)BM);
        g_flag = 0;  // reset for next graph replay
    }
}

extern "C" void kernel_launch(void* const* d_in, const int* in_sizes, int n_in,
                              void* d_out, int out_size) {
    const float* pred_xyz   = (const float*)d_in[0];  // (B,N,3)
    const float* pred_sigma = (const float*)d_in[1];  // (B,N,2)
    const float* target     = (const float*)d_in[2];  // (B,M,3)
    float* out = (float*)d_out;

    kprep<<<(BDIM * NDIM) / 128, 128>>>(pred_xyz, pred_sigma);
    kmain<<<dim3(NCHUNK, NMT, BDIM), 128>>>(target);
    kreduce<<<64, 256>>>(out);
}

// round 15
// speedup vs baseline: 1.3737x; 1.0129x over previous
#include <cuda_runtime.h>
#include <cuda_bf16.h>

// GMMLoss: nll[b,m] = -logsumexp_n( c[b,n] - 0.5*dxy/sxy - 0.5*dz/sz ), out = mean(nll)
// Proven round-5 structure (best 30.8us): 3 kernels, log2-domain, fixed LSE shift EST=40,
// expanded-quadratic 5-FMA packed-f32x2 inner loop, TN=128 / TM=512 / grid 1024x128.
// This round: PDL (programmatic dependent launch) to overlap the three kernels'
// launch latency + prologues. Bodies are unchanged.

#define BDIM 4
#define NDIM 4096
#define MDIM 4096
#define TN   128            // n per block chunk
#define NCHUNK (NDIM / TN)  // 32
#define TM   512            // m per block (128 thr * 4)
#define NMT  (MDIM / TM)    // 8
#define BM   (BDIM * MDIM)  // 16384

#define EPSF     1e-8f
#define LOG2E    1.4426950408889634f
#define LN2      0.6931471805599453f
#define LOG_2PI  1.8378762f      /* log(2*3.14159) per reference */
#define ESTC     40.0f           /* fixed log2-domain LSE shift */
#define NHALFL2E (-0.7213475f)   /* -0.5*log2e */

// Static scratch (no allocation allowed)
__device__ float g_params[BDIM * NDIM * 12];  // per n: {K,K,a2,a2, b2,b2,u,u, v,v,w,w}
__device__ float g_partial[NCHUNK * BM];      // [chunk][b*M+m]  (2 MB)
__device__ float g_bsum[64];
__device__ unsigned int g_flag;               // zero-init; self-resets each launch

// ---------- packed f32x2 helpers ----------
__device__ __forceinline__ unsigned long long pk2(float lo, float hi) {
    unsigned long long r;
    asm("mov.b64 %0, {%1, %2};" : "=l"(r) : "f"(lo), "f"(hi));
    return r;
}
__device__ __forceinline__ void unpk2(unsigned long long v, float& lo, float& hi) {
    asm("mov.b64 {%0, %1}, %2;" : "=f"(lo), "=f"(hi) : "l"(v));
}
__device__ __forceinline__ unsigned long long fma2(unsigned long long a, unsigned long long b,
                                                   unsigned long long c) {
    unsigned long long r;
    asm("fma.rn.f32x2 %0, %1, %2, %3;" : "=l"(r) : "l"(a), "l"(b), "l"(c));
    return r;
}
__device__ __forceinline__ float ex2f(float x) {
    float r;
    asm("ex2.approx.ftz.f32 %0, %1;" : "=f"(r) : "f"(x));
    return r;
}

// ---------- kernel 1: param precompute (pure map) ----------
__global__ void __launch_bounds__(256) kprep(const float* __restrict__ xyz,
                                             const float* __restrict__ sigma) {
    int idx = blockIdx.x * 256 + threadIdx.x;  // 0..16383 = b*N+n
    float2 sg = ((const float2*)sigma)[idx];
    float sxy = sg.x + EPSF;
    float sz  = sg.y + EPSF;
    float c2 = -__log2f(sxy) - 0.5f * __log2f(sz) - 1.5f * LOG_2PI * LOG2E - ESTC;
    float a2 = __fdividef(NHALFL2E, sxy);
    float b2 = __fdividef(NHALFL2E, sz);
    float px = xyz[3 * idx + 0], py = xyz[3 * idx + 1], pz = xyz[3 * idx + 2];
    float K = fmaf(a2, fmaf(px, px, py * py), fmaf(b2, pz * pz, c2));
    float u = -2.0f * a2 * px;
    float v = -2.0f * a2 * py;
    float w = -2.0f * b2 * pz;
    float4* o = (float4*)(g_params + (size_t)idx * 12);
    o[0] = make_float4(K, K, a2, a2);
    o[1] = make_float4(b2, b2, u, u);
    o[2] = make_float4(v, v, w, w);
    // allow dependent kernel to start; stores above are flushed by the trigger
    cudaTriggerProgrammaticLaunchCompletion();
}

// ---------- kernel 2: main pairwise sum-of-exp2 (2 m-pairs per thread) ----------
__global__ void __launch_bounds__(128) kmain(const float* __restrict__ tgt) {
    __shared__ float4 sm[TN * 3];  // 6 KB: duplicated per-n params
    int chunk = blockIdx.x;        // 0..31
    int mt    = blockIdx.y;        // 0..7
    int b     = blockIdx.z;        // 0..3
    int tid   = threadIdx.x;

    // --- independent work first: 4 targets per thread, packed into 2 m-pairs ---
    int m0 = mt * TM + tid;
    const float* t = tgt + (size_t)(b * MDIM + m0) * 3;
    float tx[4], ty[4], tz[4], sxyv[4], szv[4];
#pragma unroll
    for (int k = 0; k < 4; k++) {
        tx[k] = t[k * 128 * 3 + 0];
        ty[k] = t[k * 128 * 3 + 1];
        tz[k] = t[k * 128 * 3 + 2];
        sxyv[k] = fmaf(tx[k], tx[k], ty[k] * ty[k]);
        szv[k]  = tz[k] * tz[k];
    }
    unsigned long long TX0 = pk2(tx[0], tx[1]), TY0 = pk2(ty[0], ty[1]), TZ0 = pk2(tz[0], tz[1]);
    unsigned long long SXY0 = pk2(sxyv[0], sxyv[1]), SZ0 = pk2(szv[0], szv[1]);
    unsigned long long TX1 = pk2(tx[2], tx[3]), TY1 = pk2(ty[2], ty[3]), TZ1 = pk2(tz[2], tz[3]);
    unsigned long long SXY1 = pk2(sxyv[2], sxyv[3]), SZ1 = pk2(szv[2], szv[3]);

    // --- wait for kprep's params, then stage them to shared ---
    cudaGridDependencySynchronize();
    const float4* src = (const float4*)(g_params + (size_t)(b * NDIM + chunk * TN) * 12);
    for (int i = tid; i < TN * 3; i += 128) sm[i] = src[i];

    float s0 = 0.f, s1 = 0.f, s2 = 0.f, s3 = 0.f;
    __syncthreads();

#pragma unroll 4
    for (int ni = 0; ni < TN; ni++) {
        const ulonglong2* q = (const ulonglong2*)(sm + ni * 3);
        ulonglong2 q0 = q[0];  // {K,K},{a2,a2}
        ulonglong2 q1 = q[1];  // {b2,b2},{u,u}
        ulonglong2 q2 = q[2];  // {v,v},{w,w}

        // pair 0 (m0, m0+128)
        {
            unsigned long long lp = fma2(q0.y, SXY0, q0.x);
            lp = fma2(q1.x, SZ0, lp);
            lp = fma2(q1.y, TX0, lp);
            lp = fma2(q2.x, TY0, lp);
            lp = fma2(q2.y, TZ0, lp);
            float lo, hi; unpk2(lp, lo, hi);
            s0 += ex2f(lo);
            s1 += ex2f(hi);
        }
        // pair 1 (m0+256, m0+384)
        {
            unsigned long long lp = fma2(q0.y, SXY1, q0.x);
            lp = fma2(q1.x, SZ1, lp);
            lp = fma2(q1.y, TX1, lp);
            lp = fma2(q2.x, TY1, lp);
            lp = fma2(q2.y, TZ1, lp);
            float lo, hi; unpk2(lp, lo, hi);
            s2 += ex2f(lo);
            s3 += ex2f(hi);
        }
    }

    float* dst = g_partial + (size_t)chunk * BM + b * MDIM + m0;
    dst[0]   = s0;
    dst[128] = s1;
    dst[256] = s2;
    dst[384] = s3;
    cudaTriggerProgrammaticLaunchCompletion();
}

// ---------- kernel 3: chunk-sum + LSE + full reduction (last-block pattern) ----------
__global__ void __launch_bounds__(256) kreduce(float* __restrict__ out) {
    int gm = blockIdx.x * 256 + threadIdx.x;  // 0..16383
    cudaGridDependencySynchronize();  // wait for kmain's partials
    float S = 0.f;
#pragma unroll
    for (int c = 0; c < NCHUNK; c++) S += g_partial[(size_t)c * BM + gm];
    float nll = -LN2 * (ESTC + __log2f(fmaxf(S, 1e-37f)));

    __shared__ float red[256];
    red[threadIdx.x] = nll;
    __syncthreads();
    for (int s = 128; s > 0; s >>= 1) {
        if (threadIdx.x < s) red[threadIdx.x] += red[threadIdx.x + s];
        __syncthreads();
    }

    __shared__ bool islast;
    if (threadIdx.x == 0) {
        g_bsum[blockIdx.x] = red[0];
        __threadfence();
        unsigned int old = atomicAdd(&g_flag, 1u);
        islast = (old == 63u);
    }
    __syncthreads();

    if (islast && threadIdx.x == 0) {
        __threadfence();
        volatile float* bs = g_bsum;
        float acc = 0.f;
#pragma unroll
        for (int i = 0; i < 64; i++) acc += bs[i];
        out[0] = acc * (1.0f / (float)BM);
        g_flag = 0;  // reset for next graph replay
    }
}

extern "C" void kernel_launch(void* const* d_in, const int* in_sizes, int n_in,
                              void* d_out, int out_size) {
    const float* pred_xyz   = (const float*)d_in[0];  // (B,N,3)
    const float* pred_sigma = (const float*)d_in[1];  // (B,N,2)
    const float* target     = (const float*)d_in[2];  // (B,M,3)
    float* out = (float*)d_out;

    // kernel 1: normal launch
    kprep<<<(BDIM * NDIM) / 256, 256>>>(pred_xyz, pred_sigma);

    // kernels 2 & 3: PDL — overlap launch/prologue with predecessor
    cudaLaunchAttribute attr[1];
    attr[0].id = cudaLaunchAttributeProgrammaticStreamSerialization;
    attr[0].val.programmaticStreamSerializationAllowed = 1;

    {
        cudaLaunchConfig_t cfg = {};
        cfg.gridDim  = dim3(NCHUNK, NMT, BDIM);
        cfg.blockDim = dim3(128, 1, 1);
        cfg.dynamicSmemBytes = 0;
        cfg.stream = 0;
        cfg.attrs = attr;
        cfg.numAttrs = 1;
        cudaLaunchKernelEx(&cfg, kmain, target);
    }
    {
        cudaLaunchConfig_t cfg = {};
        cfg.gridDim  = dim3(64, 1, 1);
        cfg.blockDim = dim3(256, 1, 1);
        cfg.dynamicSmemBytes = 0;
        cfg.stream = 0;
        cfg.attrs = attr;
        cfg.numAttrs = 1;
        cudaLaunchKernelEx(&cfg, kreduce, out);
    }
}